// round 12
// baseline (speedup 1.0000x reference)
#include <cuda_runtime.h>

// OTAM soft-DTW, exp-domain, 4-lane wavefront split.
// dists: [256, 64, 48, 48] f32 -> out: [256, 64] f32
//
// E = exp(-cum/lbda), lbda = 0.5:
//   E_cur[m] = w[m]*(E_prev[m-1] + E_cur[m-1] (+ E_prev[m] at m==1, m==49)),
//   w = exp(-2 d) = exp2(C*d).  Row 0 == general cell with E_prev == 0.
//   answer = -0.5*ln(E_final[49]).
//
// Lane group (4p..4p+3) shares problem p. Lane q owns columns
// [12q+1 .. 12q+12] (lane 3 additionally owns pad column 49) and computes
// row t-q at wavefront step t (3-row skew). Seam values (E_cur, E_prev at
// the boundary column) pass to lane q+1 via shfl_up with one step of slack.
// 8 problems/warp -> 2048 warps (2x R11), 12-cell serial chain per step.

#define LQ 48
#define MQ 48
#define PPW 8                                // problems per warp/CTA
#define PSTRIDE (LQ * MQ)                    // 2304 floats per problem
#define PITCH4 13                            // float4 pitch (208 B) per problem-row
#define STAGE_F4 (PPW * PITCH4)              // 104 float4 = 1664 B per stage (1 row)
#define STAGE_BYTES (STAGE_F4 * 16)
#define NS 8
#define SMEM_BYTES (NS * STAGE_BYTES)        // 13312 B per CTA

__device__ __forceinline__ float ex2f(float x) {
    float y; asm("ex2.approx.f32 %0, %1;" : "=f"(y) : "f"(x)); return y;
}
__device__ __forceinline__ float lg2f(float x) {
    float y; asm("lg2.approx.f32 %0, %1;" : "=f"(y) : "f"(x)); return y;
}
__device__ __forceinline__ void cp_async16_s(unsigned smem_dst, const void* gsrc) {
    asm volatile("cp.async.cg.shared.global [%0], [%1], 16;\n"
                 :: "r"(smem_dst), "l"(gsrc) : "memory");
}

extern __shared__ float4 smem4[];

__global__ void __launch_bounds__(32, 1)
otam_kernel(const float* __restrict__ dists, float* __restrict__ out) {
    const int lane = threadIdx.x;
    const int q    = lane & 3;               // quarter (column block) index
    const int p    = lane >> 2;              // problem index within warp
    const int pbase = blockIdx.x * PPW;
    const float* gbase = dists + (size_t)pbase * PSTRIDE;

    // Staging map: one row = 8 problems x 192 B = 96 chunks of 16 B, 3/lane.
    // chunk ch = lane + 32k -> problem pp = ch/12, segment j = ch%12.
    // Global side: contiguous 192 B per problem-row -> coalesced.
    int sgo[3]; unsigned sso[3];
    const unsigned sbase = (unsigned)__cvta_generic_to_shared(smem4);
#pragma unroll
    for (int k = 0; k < 3; k++) {
        int ch = lane + k * 32;
        int pp = ch / 12;
        int j  = ch - pp * 12;
        sgo[k] = pp * PSTRIDE + j * 4;
        sso[k] = sbase + (unsigned)(pp * PITCH4 + j) * 16u;
    }

    // Prologue: rows 0..NS-1 into stages 0..NS-1 (group index == row index).
#pragma unroll
    for (int s = 0; s < NS; s++) {
        const float* gr = gbase + s * MQ;
#pragma unroll
        for (int k = 0; k < 3; k++)
            cp_async16_s(sso[k] + (unsigned)(s * STAGE_BYTES), gr + sgo[k]);
        asm volatile("cp.async.commit_group;\n" ::: "memory");
    }

    const float C = -2.885390081777927f;     // -2/ln2 : exp2(C*d) = exp(-2d)

    // F: lane q holds E[12q+1 .. 12q+12] in F[0..11]; lane 3 also E[49] in F[12].
    float F[13];
#pragma unroll
    for (int i = 0; i < 13; i++) F[i] = 0.f;

    float c = 0.f, diag = 0.f;               // this lane's seam outputs
    float cin = 0.f, din = 0.f;              // received seam (consumed next step)

    // Per-lane read base within a stage (float4 units).
    const int rbase = p * PITCH4 + q * 3;

#pragma unroll 1
    for (int t = 0; t <= LQ + 2; t++) {      // 51 wavefront steps
        // Commits before step t = NS + max(0, t-3); group r carries row r.
        // Need group (t) done for lane 0 -> pending <= NS-4 suffices for all t.
        asm volatile("cp.async.wait_group %0;\n" :: "n"(NS - 4) : "memory");
        __syncwarp();

        const int r = t - q;                 // row this lane computes
        const bool act = (r >= 0) && (r < LQ);

        if (act) {
            int st = r & (NS - 1);
            const float4* rp = smem4 + st * STAGE_F4 + rbase;
            float4 q0 = rp[0], q1 = rp[1], q2 = rp[2];

            if (q == 0) { c = 1.f; diag = (r == 0) ? 0.f : 1.f; }
            else        { c = cin; diag = din; }

#define CELLR(W, I) { float tt = F[I]; float wd = (W) * diag; \
                      c = fmaf((W), c, wd); diag = tt; F[I] = c; }
            // cell 0: lane 0 has the m==1 edge include (E_prev[1] = old F[0]).
            {
                float w0 = ex2f(q0.x * C);
                float tt = F[0];
                float wd = w0 * diag;
                float ce = fmaf(w0, c, wd);
                if (q == 0) ce = fmaf(w0, tt, ce);
                c = ce; diag = tt; F[0] = c;
            }
            {
                float w1 = ex2f(q0.y * C), w2 = ex2f(q0.z * C), w3 = ex2f(q0.w * C);
                CELLR(w1, 1) CELLR(w2, 2) CELLR(w3, 3)
            }
            {
                float w0 = ex2f(q1.x * C), w1 = ex2f(q1.y * C);
                float w2 = ex2f(q1.z * C), w3 = ex2f(q1.w * C);
                CELLR(w0, 4) CELLR(w1, 5) CELLR(w2, 6) CELLR(w3, 7)
            }
            {
                float w0 = ex2f(q2.x * C), w1 = ex2f(q2.y * C);
                float w2 = ex2f(q2.z * C), w3 = ex2f(q2.w * C);
                CELLR(w0, 8) CELLR(w1, 9) CELLR(w2, 10) CELLR(w3, 11)
            }
#undef CELLR
            // lane 3 pad cell m==49: w = 1, edge include E_prev[49] (old F[12]).
            if (q == 3) { float tt = F[12]; c = diag + c + tt; F[12] = c; }
        }

        // Seam handoff to lane q+1 (consumed at the NEXT step).
        float nc = __shfl_up_sync(0xffffffffu, c,    1);
        float nd = __shfl_up_sync(0xffffffffu, diag, 1);
        if (q != 0) { cin = nc; din = nd; }

        __syncwarp();                        // stage (t-3)%NS fully read
        if (t >= 3) {
            int row = t + NS - 3;
            if (row < LQ) {
                const float* gr = gbase + row * MQ;
                unsigned sb = (unsigned)(((t - 3) & (NS - 1)) * STAGE_BYTES);
#pragma unroll
                for (int k = 0; k < 3; k++)
                    cp_async16_s(sso[k] + sb, gr + sgo[k]);
            }
            asm volatile("cp.async.commit_group;\n" ::: "memory");  // empty ok
        }
    }

    if (q == 3)
        out[pbase + p] = -0.34657359027997264f * lg2f(F[12]);
}

extern "C" void kernel_launch(void* const* d_in, const int* in_sizes, int n_in,
                              void* d_out, int out_size) {
    const float* dists = (const float*)d_in[0];
    float* out = (float*)d_out;
    int B = in_sizes[0] / PSTRIDE;           // 16384 problems
    int grid = B / PPW;                      // 2048 CTAs (1 warp each)

    cudaFuncSetAttribute(otam_kernel, cudaFuncAttributeMaxDynamicSharedMemorySize,
                         SMEM_BYTES);
    otam_kernel<<<grid, 32, SMEM_BYTES>>>(dists, out);
}

// round 13
// speedup vs baseline: 1.0077x; 1.0077x over previous
#include <cuda_runtime.h>

// OTAM soft-DTW, exp-domain, 2-lane wavefront split + 3-row grouped staging.
// dists: [256, 64, 48, 48] f32 -> out: [256, 64] f32
//
// E = exp(-cum/lbda), lbda = 0.5:
//   E_cur[m] = w[m]*(E_prev[m-1] + E_cur[m-1] (+ E_prev[m] at m==1, m==49)),
//   w = exp(-2 d) = exp2(C*d).  Row 0 == general cell with E_prev == 0.
//   answer = -0.5*ln(E_final[49]).
//
// Lane pair (2p, 2p+1): even lane (A) computes m=1..24 of row t, odd lane (B)
// m=25..49 of row t-1. Staging fetches GROUPS of 3 consecutive rows per
// problem (576 B contiguous -> much better HBM row locality than 192 B), ring
// of 3 slots, one wait/sync/refill per 3 wavefront steps.

#define LQ 48
#define MQ 48
#define PPW 16                                // problems per warp/CTA
#define PSTRIDE (LQ * MQ)                     // 2304 floats per problem
#define GR 3                                  // rows per staging group
#define NG 16                                 // total groups (48 rows)
#define RING 3
#define RPITCH4 14                            // float4 pitch per row (A at +0..5, B at +7..12)
#define PPITCH4 (GR * RPITCH4)                // 42 float4 per problem per slot
#define SLOT_F4 (PPW * PPITCH4)               // 672
#define SLOT_BYTES (SLOT_F4 * 16)             // 10752
#define SMEM_BYTES (RING * SLOT_BYTES)        // 32256 B -> 7 CTAs/SM

__device__ __forceinline__ float ex2f(float x) {
    float y; asm("ex2.approx.f32 %0, %1;" : "=f"(y) : "f"(x)); return y;
}
__device__ __forceinline__ float lg2f(float x) {
    float y; asm("lg2.approx.f32 %0, %1;" : "=f"(y) : "f"(x)); return y;
}
__device__ __forceinline__ void cp_async16_s(unsigned smem_dst, const void* gsrc) {
    asm volatile("cp.async.cg.shared.global [%0], [%1], 16;\n"
                 :: "r"(smem_dst), "l"(gsrc) : "memory");
}

extern __shared__ float4 smem4[];

// One DP wavefront step for this lane's 24 columns. c/diag must be
// pre-initialized by the caller (A: 1 / 0-or-1; B: seam handoff).
__device__ __forceinline__ void dp_step(const float4* __restrict__ rp,
                                        float* __restrict__ F,
                                        float& c, float& diag, int half) {
    float4 a0 = rp[0], a1 = rp[1], a2 = rp[2], a3 = rp[3], a4 = rp[4], a5 = rp[5];
#define CELLR(W, I) { float tt = F[I]; float wd = (W) * diag; \
                      c = fmaf((W), c, wd); diag = tt; F[I] = c; }
    {   // first cell: A has the m==1 edge include (E_prev[1] = old F[0]).
        float w0 = ex2f(a0.x * -2.885390081777927f);
        float tt = F[0];
        float ss = diag + c;
        if (!half) ss += tt;
        c = w0 * ss; diag = tt; F[0] = c;
    }
#define GRP(Q, B0) { float w0 = ex2f((Q).x * -2.885390081777927f); \
                     float w1 = ex2f((Q).y * -2.885390081777927f); \
                     float w2 = ex2f((Q).z * -2.885390081777927f); \
                     float w3 = ex2f((Q).w * -2.885390081777927f); \
                     CELLR(w0, (B0)) CELLR(w1, (B0)+1) CELLR(w2, (B0)+2) CELLR(w3, (B0)+3) }
    {   float w1 = ex2f(a0.y * -2.885390081777927f);
        float w2 = ex2f(a0.z * -2.885390081777927f);
        float w3 = ex2f(a0.w * -2.885390081777927f);
        CELLR(w1, 1) CELLR(w2, 2) CELLR(w3, 3) }
    GRP(a1, 4) GRP(a2, 8) GRP(a3, 12) GRP(a4, 16) GRP(a5, 20)
#undef GRP
#undef CELLR
    // B pad cell m==49: w = 1, edge include E_prev[49] (old F[24]).
    if (half) { float tt = F[24]; c = diag + c + tt; F[24] = c; }
}

__global__ void __launch_bounds__(32, 1)
otam_kernel(const float* __restrict__ dists, float* __restrict__ out) {
    const int lane = threadIdx.x;
    const int half = lane & 1;               // 0: A (cols 1..24), 1: B (25..49)
    const int p    = lane >> 1;              // problem within warp
    const int pbase = blockIdx.x * PPW;
    const float* gbase = dists + (size_t)pbase * PSTRIDE;

    // Staging map: one group = 16 problems x 576 B contiguous = 576 chunks of
    // 16 B, 18 per lane. chunk ch = lane + 32k -> problem pp = ch/36,
    // j = ch%36 (float4 within problem-group). Smem: row jr = j/12 at pitch
    // 14, segment js = j%12 stored at js (<6) or js+1 (>=6) -> B half at +7.
    int sgo[18]; unsigned sso[18];
    const unsigned sbase = (unsigned)__cvta_generic_to_shared(smem4);
#pragma unroll
    for (int k = 0; k < 18; k++) {
        int ch = lane + 32 * k;
        int pp = ch / 36;
        int j  = ch - 36 * pp;
        int jr = j / 12, js = j - 12 * jr;
        int js2 = js + (js >= 6 ? 1 : 0);
        sgo[k] = pp * PSTRIDE + j * 4;       // float offset within a group-plane
        sso[k] = sbase + (unsigned)(pp * PPITCH4 + jr * RPITCH4 + js2) * 16u;
    }

    // Prologue: groups 0..2 -> slots 0..2 (3 commits).
#pragma unroll
    for (int s = 0; s < RING; s++) {
        const float* gp = gbase + s * (GR * MQ);
#pragma unroll
        for (int k = 0; k < 18; k++)
            cp_async16_s(sso[k] + (unsigned)(s * SLOT_BYTES), gp + sgo[k]);
        asm volatile("cp.async.commit_group;\n" ::: "memory");
    }

    float F[25];
#pragma unroll
    for (int i = 0; i < 25; i++) F[i] = 0.f;
    float c = 0.f, diag = 0.f;               // seam outputs (A -> B)
    float cin = 0.f, din = 0.f;              // B's received seam

    const int rbase = p * PPITCH4;           // float4 units within a slot
    const int hoff  = half * 7;

#pragma unroll 1
    for (int g = 0; g < NG; g++) {
        // Commit ledger: 3 prologue + one per prior group = 3+g commits;
        // group g is commit #(g+2) -> <=1 pending lands exactly groups 0..g.
        asm volatile("cp.async.wait_group 1;\n" ::: "memory");
        __syncwarp();
        const int s0 = g % 3;                // slot of group g
        const int s2 = (g + 2) % 3;          // slot of group g-1 == refill target

#pragma unroll
        for (int rr = 0; rr < 3; rr++) {
            const int t = 3 * g + rr;
            // A reads row t = group g row rr; B reads row t-1:
            //   rr==0 -> group g-1 row 2 (slot s2), else group g row rr-1.
            int sl = half ? ((rr == 0) ? s2 : s0) : s0;
            int rw = half ? ((rr == 0) ? 2 : rr - 1) : rr;
            const bool act = half ? (t >= 1) : true;
            if (act) {
                const float4* rp = smem4 + sl * SLOT_F4 + rbase + rw * RPITCH4 + hoff;
                if (half == 0) { c = 1.f; diag = (t == 0) ? 0.f : 1.f; }
                else           { c = cin; diag = din; }
                dp_step(rp, F, c, diag, half);
            }
            // Seam handoff (consumed by B next step).
            float nc = __shfl_sync(0xffffffffu, c,    lane & ~1);
            float nd = __shfl_sync(0xffffffffu, diag, lane & ~1);
            if (half) { cin = nc; din = nd; }

            if (rr == 0) {
                // B just consumed the last row of group g-1 -> slot s2 free.
                __syncwarp();
                int G = g + 2;
                if (G >= RING && G < NG) {
                    const float* gp = gbase + G * (GR * MQ);
                    unsigned sb = (unsigned)(s2 * SLOT_BYTES);
#pragma unroll
                    for (int k = 0; k < 18; k++)
                        cp_async16_s(sso[k] + sb, gp + sgo[k]);
                }
                asm volatile("cp.async.commit_group;\n" ::: "memory");  // empty ok
            }
        }
    }

    // Epilogue step t=48: B computes row 47 (group 15 -> slot 0, row 2).
    if (half) {
        const float4* rp = smem4 + /*slot*/0 * SLOT_F4 + rbase + 2 * RPITCH4 + hoff;
        c = cin; diag = din;
        dp_step(rp, F, c, diag, 1);
        out[pbase + p] = -0.34657359027997264f * lg2f(F[24]);
    }
}

extern "C" void kernel_launch(void* const* d_in, const int* in_sizes, int n_in,
                              void* d_out, int out_size) {
    const float* dists = (const float*)d_in[0];
    float* out = (float*)d_out;
    int B = in_sizes[0] / PSTRIDE;           // 16384 problems
    int grid = B / PPW;                      // 1024 CTAs (1 warp each)

    cudaFuncSetAttribute(otam_kernel, cudaFuncAttributeMaxDynamicSharedMemorySize,
                         SMEM_BYTES);
    otam_kernel<<<grid, 32, SMEM_BYTES>>>(dists, out);
}